// round 1
// baseline (speedup 1.0000x reference)
#include <cuda_runtime.h>
#include <math.h>

#define Nn 50000
#define Ee 500000
#define Tt 8
#define Rr 8

// dynamic smem: Xs[128][68] + Ws[128][128], fp32
#define DSMEM_BYTES ((128*68 + 128*128)*4)

// ---------------- device scratch (static globals; no allocation) ----------------
__device__ float g_k[(long long)Nn*128];
__device__ float g_q[(long long)Nn*128];
__device__ float g_v[(long long)Nn*128];
__device__ float g_kA[(long long)Rr*Nn*128];   // 204.8 MB
__device__ float g_vM[(long long)Rr*Nn*128];   // 204.8 MB
__device__ float g_score[Ee];
__device__ float g_ex[Ee];
__device__ unsigned g_segmax[Nn*Rr];
__device__ float g_denom[Nn*Rr];
__device__ float g_agg[(long long)Nn*128];
__device__ int g_bucket[Nn];
__device__ int g_cnt[Tt];
__device__ int g_off[Tt+1];
__device__ int g_cursor[Tt];

// ---------------- helpers ----------------
__device__ __forceinline__ unsigned long long pack2(float x, float y){
    unsigned long long r;
    asm("mov.b64 %0, {%1,%2};" : "=l"(r) : "f"(x), "f"(y));
    return r;
}
__device__ __forceinline__ void fma2(unsigned long long &d, unsigned long long a, unsigned long long b){
    asm("fma.rn.f32x2 %0, %1, %2, %0;" : "+l"(d) : "l"(a), "l"(b));
}
__device__ __forceinline__ float2 unpack2(unsigned long long v){
    float x, y;
    asm("mov.b64 {%0,%1}, %2;" : "=f"(x), "=f"(y) : "l"(v));
    return make_float2(x, y);
}

// order-preserving float<->uint for atomicMax
__device__ __forceinline__ unsigned ford(float f){
    unsigned u = __float_as_uint(f);
    return (u & 0x80000000u) ? ~u : (u | 0x80000000u);
}
__device__ __forceinline__ float ordf(unsigned u){
    return (u & 0x80000000u) ? __uint_as_float(u & 0x7fffffffu) : __uint_as_float(~u);
}

// ---------------- GEMM tile machinery (64 rows x 128 cols, K=128) ----------------
// 128 threads: rg = tid>>4 (8 row groups of 8), cg = tid&15 (16 col groups of 8)

__device__ __forceinline__ void stage_rows(float* Xs, const float* __restrict__ X,
                                           const int* rows_s, int mc, int tid){
    // Xs layout: [d][m], ld=68 (pad keeps float4 alignment, spreads banks)
    #pragma unroll 4
    for (int m = 0; m < 64; m++){
        float v = 0.f;
        if (m < mc) v = X[(long long)rows_s[m]*128 + tid];
        Xs[tid*68 + m] = v;
    }
}

__device__ __forceinline__ void stage_W(float* Ws, const float* __restrict__ W, int tid){
    const float4* s = reinterpret_cast<const float4*>(W);
    float4* d4 = reinterpret_cast<float4*>(Ws);
    #pragma unroll
    for (int i = 0; i < 32; i++) d4[i*128 + tid] = s[i*128 + tid];
}

__device__ __forceinline__ void gemm_tile(const float* __restrict__ Xs,
                                          const float* __restrict__ Ws,
                                          unsigned long long acc[8][4],
                                          int rg, int cg){
    #pragma unroll
    for (int i = 0; i < 8; i++)
        #pragma unroll
        for (int j = 0; j < 4; j++) acc[i][j] = 0ull;

    #pragma unroll 4
    for (int d = 0; d < 128; d++){
        const float4* ap = reinterpret_cast<const float4*>(Xs + d*68 + rg*8);
        float4 a0 = ap[0], a1 = ap[1];
        const float4* bp = reinterpret_cast<const float4*>(Ws + d*128 + cg*8);
        float4 b0 = bp[0], b1 = bp[1];
        unsigned long long bb0 = pack2(b0.x, b0.y);
        unsigned long long bb1 = pack2(b0.z, b0.w);
        unsigned long long bb2 = pack2(b1.x, b1.y);
        unsigned long long bb3 = pack2(b1.z, b1.w);
        float av[8] = {a0.x, a0.y, a0.z, a0.w, a1.x, a1.y, a1.z, a1.w};
        #pragma unroll
        for (int i = 0; i < 8; i++){
            unsigned long long aa = pack2(av[i], av[i]);
            fma2(acc[i][0], aa, bb0);
            fma2(acc[i][1], aa, bb1);
            fma2(acc[i][2], aa, bb2);
            fma2(acc[i][3], aa, bb3);
        }
    }
}

__device__ __forceinline__ void write_tile(float* __restrict__ C, const int* rows_s, int mc,
                                           unsigned long long acc[8][4], int rg, int cg, float gate){
    #pragma unroll
    for (int i = 0; i < 8; i++){
        int m = rg*8 + i;
        if (m < mc){
            float2 p0 = unpack2(acc[i][0]);
            float2 p1 = unpack2(acc[i][1]);
            float2 p2 = unpack2(acc[i][2]);
            float2 p3 = unpack2(acc[i][3]);
            float4* op = reinterpret_cast<float4*>(C + (long long)rows_s[m]*128 + cg*8);
            op[0] = make_float4(p0.x*gate, p0.y*gate, p1.x*gate, p1.y*gate);
            op[1] = make_float4(p2.x*gate, p2.y*gate, p3.x*gate, p3.y*gate);
        }
    }
}

// ---------------- init / bucketing ----------------
__global__ void init_kernel(){
    int i = blockIdx.x * 256 + threadIdx.x;
    if (i < Nn*128) g_agg[i] = 0.f;
    if (i < Nn*Rr){ g_denom[i] = 0.f; g_segmax[i] = 0u; }
    if (i < Tt) g_cnt[i] = 0;
}

__global__ void hist_kernel(const int* __restrict__ nt){
    int n = blockIdx.x * 256 + threadIdx.x;
    if (n < Nn) atomicAdd(&g_cnt[nt[n]], 1);
}

__global__ void prefix_kernel(){
    if (threadIdx.x == 0){
        int s = 0;
        for (int t = 0; t < Tt; t++){
            g_off[t] = s;
            g_cursor[t] = s;
            s += g_cnt[t];
        }
        g_off[Tt] = s;
    }
}

__global__ void scatter_kernel(const int* __restrict__ nt){
    int n = blockIdx.x * 256 + threadIdx.x;
    if (n < Nn){
        int p = atomicAdd(&g_cursor[nt[n]], 1);
        g_bucket[p] = n;
    }
}

// ---------------- K1: per-type fused k/q/v projection ----------------
__global__ void __launch_bounds__(128) proj_kqv_kernel(
    const float* __restrict__ h,
    const float* __restrict__ kw, const float* __restrict__ qw, const float* __restrict__ vw,
    float* __restrict__ ok, float* __restrict__ oq, float* __restrict__ ov)
{
    extern __shared__ float sm[];
    float* Xs = sm;
    float* Ws = sm + 128*68;
    __shared__ int rows_s[64];

    int tid = threadIdx.x;
    int t = blockIdx.y;
    int base = g_off[t];
    int cnt = g_off[t+1] - base;
    int tb = blockIdx.x * 64;
    if (tb >= cnt) return;
    int mc = min(64, cnt - tb);

    if (tid < 64) rows_s[tid] = (tid < mc) ? g_bucket[base + tb + tid] : 0;
    __syncthreads();
    stage_rows(Xs, h, rows_s, mc, tid);

    const float* Wsrc[3] = { kw + t*16384, qw + t*16384, vw + t*16384 };
    float* Cd[3] = { ok, oq, ov };
    int rg = tid >> 4, cg = tid & 15;

    for (int w = 0; w < 3; w++){
        __syncthreads();                 // Xs ready / previous Ws readers done
        stage_W(Ws, Wsrc[w], tid);
        __syncthreads();
        unsigned long long acc[8][4];
        gemm_tile(Xs, Ws, acc, rg, cg);
        write_tile(Cd[w], rows_s, mc, acc, rg, cg, 1.0f);
    }
}

// ---------------- K2: per-relation dense GEMM (C[r] = X @ W[r]) ----------------
__global__ void __launch_bounds__(128) relproj_kernel(
    const float* __restrict__ X, const float* __restrict__ Wall, float* __restrict__ Call)
{
    extern __shared__ float sm[];
    float* Xs = sm;
    float* Ws = sm + 128*68;
    __shared__ int rows_s[64];

    int tid = threadIdx.x;
    int r = blockIdx.y;
    int tb = blockIdx.x * 64;
    int mc = min(64, Nn - tb);

    if (tid < 64) rows_s[tid] = tb + tid;
    __syncthreads();
    stage_rows(Xs, X, rows_s, mc, tid);
    stage_W(Ws, Wall + r*16384, tid);
    __syncthreads();

    int rg = tid >> 4, cg = tid & 15;
    unsigned long long acc[8][4];
    gemm_tile(Xs, Ws, acc, rg, cg);
    write_tile(Call + (long long)r*Nn*128, rows_s, mc, acc, rg, cg, 1.0f);
}

// ---------------- K3: per-edge score + segment max ----------------
__global__ void __launch_bounds__(256) score_kernel(
    const float* __restrict__ kA, const float* __restrict__ q,
    const int* __restrict__ src, const int* __restrict__ dst, const int* __restrict__ et,
    const float* __restrict__ pri, float* __restrict__ score, unsigned* __restrict__ segmax)
{
    int e = (blockIdx.x * blockDim.x + threadIdx.x) >> 5;
    if (e >= Ee) return;
    int lane = threadIdx.x & 31;
    int s = src[e], d = dst[e], r = et[e];
    const float4* ka = reinterpret_cast<const float4*>(kA + ((long long)r*Nn + s)*128);
    const float4* qq = reinterpret_cast<const float4*>(q + (long long)d*128);
    float4 x = ka[lane], y = qq[lane];
    float acc = x.x*y.x + x.y*y.y + x.z*y.z + x.w*y.w;
    #pragma unroll
    for (int o = 16; o; o >>= 1) acc += __shfl_xor_sync(0xffffffffu, acc, o);
    if (lane == 0){
        float sc = acc * pri[r] * 0.08838834764831845f;  // 1/sqrt(128)
        score[e] = sc;
        atomicMax(&segmax[d*Rr + r], ford(sc));
    }
}

// ---------------- K4: exp + denom ----------------
__global__ void __launch_bounds__(256) exp_kernel(
    const float* __restrict__ score, const int* __restrict__ dst, const int* __restrict__ et,
    const unsigned* __restrict__ segmax, float* __restrict__ denom, float* __restrict__ ex)
{
    int e = blockIdx.x * 256 + threadIdx.x;
    if (e >= Ee) return;
    int seg = dst[e]*Rr + et[e];
    float m = ordf(segmax[seg]);
    float v = expf(score[e] - m);
    ex[e] = v;
    atomicAdd(&denom[seg], v);
}

// ---------------- K5: weighted aggregation ----------------
__global__ void __launch_bounds__(256) agg_kernel(
    const float* __restrict__ vM, const float* __restrict__ ex, const float* __restrict__ denom,
    const int* __restrict__ src, const int* __restrict__ dst, const int* __restrict__ et,
    float* __restrict__ agg)
{
    int e = (blockIdx.x * blockDim.x + threadIdx.x) >> 5;
    if (e >= Ee) return;
    int lane = threadIdx.x & 31;
    int s = src[e], d = dst[e], r = et[e];
    float alpha = ex[e] / denom[d*Rr + et[e]];
    const float4* vm = reinterpret_cast<const float4*>(vM + ((long long)r*Nn + s)*128);
    float4 v = vm[lane];
    float* out = agg + (long long)d*128 + lane*4;
    atomicAdd(out + 0, alpha * v.x);
    atomicAdd(out + 1, alpha * v.y);
    atomicAdd(out + 2, alpha * v.z);
    atomicAdd(out + 3, alpha * v.w);
}

// ---------------- K6: per-type output transform with sigmoid(skip) gate ----------------
__global__ void __launch_bounds__(128) out_kernel(
    const float* __restrict__ agg, const float* __restrict__ aw,
    const float* __restrict__ skip, float* __restrict__ out)
{
    extern __shared__ float sm[];
    float* Xs = sm;
    float* Ws = sm + 128*68;
    __shared__ int rows_s[64];

    int tid = threadIdx.x;
    int t = blockIdx.y;
    int base = g_off[t];
    int cnt = g_off[t+1] - base;
    int tb = blockIdx.x * 64;
    if (tb >= cnt) return;
    int mc = min(64, cnt - tb);

    if (tid < 64) rows_s[tid] = (tid < mc) ? g_bucket[base + tb + tid] : 0;
    __syncthreads();
    stage_rows(Xs, agg, rows_s, mc, tid);
    stage_W(Ws, aw + t*16384, tid);
    __syncthreads();

    float gate = 1.f / (1.f + expf(-skip[t]));
    int rg = tid >> 4, cg = tid & 15;
    unsigned long long acc[8][4];
    gemm_tile(Xs, Ws, acc, rg, cg);
    write_tile(out, rows_s, mc, acc, rg, cg, gate);
}

// ---------------- launch ----------------
extern "C" void kernel_launch(void* const* d_in, const int* in_sizes, int n_in,
                              void* d_out, int out_size)
{
    const float* h     = (const float*)d_in[0];
    const int*   adj   = (const int*)d_in[1];
    const int*   etype = (const int*)d_in[2];
    const int*   ntype = (const int*)d_in[3];
    const float* kw    = (const float*)d_in[6];
    const float* qw    = (const float*)d_in[7];
    const float* vw    = (const float*)d_in[8];
    const float* aw    = (const float*)d_in[9];
    const float* pri   = (const float*)d_in[10];
    const float* att   = (const float*)d_in[11];
    const float* msg   = (const float*)d_in[12];
    const float* skip  = (const float*)d_in[13];
    const int* src = adj;
    const int* dst = adj + Ee;
    float* out = (float*)d_out;

    cudaFuncSetAttribute(proj_kqv_kernel, cudaFuncAttributeMaxDynamicSharedMemorySize, DSMEM_BYTES);
    cudaFuncSetAttribute(relproj_kernel,  cudaFuncAttributeMaxDynamicSharedMemorySize, DSMEM_BYTES);
    cudaFuncSetAttribute(out_kernel,      cudaFuncAttributeMaxDynamicSharedMemorySize, DSMEM_BYTES);

    void *pk, *pq, *pv, *pkA, *pvM, *pscore, *pex, *psegmax, *pdenom, *pagg;
    cudaGetSymbolAddress(&pk, g_k);
    cudaGetSymbolAddress(&pq, g_q);
    cudaGetSymbolAddress(&pv, g_v);
    cudaGetSymbolAddress(&pkA, g_kA);
    cudaGetSymbolAddress(&pvM, g_vM);
    cudaGetSymbolAddress(&pscore, g_score);
    cudaGetSymbolAddress(&pex, g_ex);
    cudaGetSymbolAddress(&psegmax, g_segmax);
    cudaGetSymbolAddress(&pdenom, g_denom);
    cudaGetSymbolAddress(&pagg, g_agg);

    // init + bucketing
    init_kernel<<<(Nn*128 + 255)/256, 256>>>();
    hist_kernel<<<(Nn + 255)/256, 256>>>(ntype);
    prefix_kernel<<<1, 32>>>();
    scatter_kernel<<<(Nn + 255)/256, 256>>>(ntype);

    dim3 gT((Nn + 63)/64, Tt);
    proj_kqv_kernel<<<gT, 128, DSMEM_BYTES>>>(h, kw, qw, vw,
                                              (float*)pk, (float*)pq, (float*)pv);

    dim3 gR((Nn + 63)/64, Rr);
    relproj_kernel<<<gR, 128, DSMEM_BYTES>>>((const float*)pk, att, (float*)pkA);
    relproj_kernel<<<gR, 128, DSMEM_BYTES>>>((const float*)pv, msg, (float*)pvM);

    int score_blocks = (Ee + 7) / 8;   // 8 warps/block, warp per edge
    score_kernel<<<score_blocks, 256>>>((const float*)pkA, (const float*)pq,
                                        src, dst, etype, pri,
                                        (float*)pscore, (unsigned*)psegmax);

    exp_kernel<<<(Ee + 255)/256, 256>>>((const float*)pscore, dst, etype,
                                        (const unsigned*)psegmax,
                                        (float*)pdenom, (float*)pex);

    agg_kernel<<<score_blocks, 256>>>((const float*)pvM, (const float*)pex,
                                      (const float*)pdenom, src, dst, etype,
                                      (float*)pagg);

    out_kernel<<<gT, 128, DSMEM_BYTES>>>((const float*)pagg, aw, skip, out);
}

// round 3
// speedup vs baseline: 1.2843x; 1.2843x over previous
#include <cuda_runtime.h>
#include <mma.h>
#include <math.h>
#include <cstdint>

using namespace nvcuda;

#define Nn 50000
#define Ee 500000
#define Tt 8
#define Rr 8
#define NT 391                 // ceil(50000/128) row tiles
#define NP (NT*128)            // padded rows = 50048

// GEMM smem: As[128][132] fp32 + Bs[64][132] fp32 (Bs doubles as C staging)
#define AS_LD 132
#define BS_LD 132
#define SM_AS (128*AS_LD)          // floats
#define SM_BS (64*BS_LD)           // floats
#define GEMM_SMEM ((SM_AS + SM_BS)*4)

// ---------------- device scratch (static globals; no allocation) ----------------
__device__ float g_k[(size_t)NP*128];
__device__ float g_q[(size_t)Nn*128];
__device__ float g_v[(size_t)NP*128];
__device__ float g_kA[(size_t)Rr*NP*128];   // padded: direct wmma stores
__device__ float g_vM[(size_t)Rr*NP*128];
__device__ float g_score[Ee];
__device__ float g_ex[Ee];
__device__ unsigned g_segmax[Nn*Rr];
__device__ float g_denom[Nn*Rr];
__device__ float g_agg[(size_t)Nn*128];
__device__ int g_bucket[Nn];
__device__ int g_cnt[Tt];
__device__ int g_off[Tt+1];
__device__ int g_cursor[Tt];

// ---------------- helpers ----------------
__device__ __forceinline__ float to_tf32(float x){
    float r;
    asm("cvt.rna.tf32.f32 %0, %1;" : "=f"(r) : "f"(x));
    return r;
}
__device__ __forceinline__ unsigned ford(float f){
    unsigned u = __float_as_uint(f);
    return (u & 0x80000000u) ? ~u : (u | 0x80000000u);
}
__device__ __forceinline__ float ordf(unsigned u){
    return (u & 0x80000000u) ? __uint_as_float(u & 0x7fffffffu) : __uint_as_float(~u);
}

typedef wmma::fragment<wmma::matrix_a, 16, 16, 8, wmma::precision::tf32, wmma::row_major> FragA;
typedef wmma::fragment<wmma::matrix_b, 16, 16, 8, wmma::precision::tf32, wmma::row_major> FragB;
typedef wmma::fragment<wmma::accumulator, 16, 16, 8, float> FragC;

__device__ __forceinline__ void split_a(const FragA& raw, FragA& hi, FragA& lo){
    #pragma unroll
    for (int i = 0; i < raw.num_elements; i++){
        float x = raw.x[i];
        float h = to_tf32(x);
        hi.x[i] = h;
        lo.x[i] = to_tf32(x - h);
    }
}
__device__ __forceinline__ void split_b(const FragB& raw, FragB& hi, FragB& lo){
    #pragma unroll
    for (int i = 0; i < raw.num_elements; i++){
        float x = raw.x[i];
        float h = to_tf32(x);
        hi.x[i] = h;
        lo.x[i] = to_tf32(x - h);
    }
}

// stage 64 rows x 128 cols of W (row-major, ld 128) into Bs[64][BS_LD]
__device__ __forceinline__ void stage_B(float* Bs, const float* __restrict__ W, int tid){
    #pragma unroll
    for (int i = 0; i < 8; i++){
        int idx = tid + i*256;            // 0..2047
        int row = idx >> 5, c4 = idx & 31;
        float4 v = *reinterpret_cast<const float4*>(W + row*128 + c4*4);
        *reinterpret_cast<float4*>(Bs + row*BS_LD + c4*4) = v;
    }
}

// run the 3xTF32 k-loop for one 64-wide K chunk; accumulate into cf[8]
__device__ __forceinline__ void mma_chunk(const float* As, const float* Bs,
                                          FragC cf[8], int wrow0, int kbase){
    FragA ar, ah, al;
    FragB br, bh, bl;
    #pragma unroll
    for (int kk = 0; kk < 64; kk += 8){
        wmma::load_matrix_sync(ar, As + wrow0*AS_LD + kbase + kk, AS_LD);
        split_a(ar, ah, al);
        #pragma unroll
        for (int nt = 0; nt < 8; nt++){
            wmma::load_matrix_sync(br, Bs + kk*BS_LD + nt*16, BS_LD);
            split_b(br, bh, bl);
            wmma::mma_sync(cf[nt], al, bh, cf[nt]);
            wmma::mma_sync(cf[nt], ah, bl, cf[nt]);
            wmma::mma_sync(cf[nt], ah, bh, cf[nt]);
        }
    }
}

// ---------------- init / bucketing ----------------
__global__ void init_kernel(){
    int i = blockIdx.x * 256 + threadIdx.x;
    if (i < Nn*128) g_agg[i] = 0.f;
    if (i < Nn*Rr){ g_denom[i] = 0.f; g_segmax[i] = 0u; }
    if (i < Tt) g_cnt[i] = 0;
}
__global__ void hist_kernel(const int* __restrict__ nt){
    int n = blockIdx.x * 256 + threadIdx.x;
    if (n < Nn) atomicAdd(&g_cnt[nt[n]], 1);
}
__global__ void prefix_kernel(){
    if (threadIdx.x == 0){
        int s = 0;
        for (int t = 0; t < Tt; t++){
            g_off[t] = s; g_cursor[t] = s; s += g_cnt[t];
        }
        g_off[Tt] = s;
    }
}
__global__ void scatter_kernel(const int* __restrict__ nt){
    int n = blockIdx.x * 256 + threadIdx.x;
    if (n < Nn){
        int p = atomicAdd(&g_cursor[nt[n]], 1);
        g_bucket[p] = n;
    }
}

// ---------------- K1: per-type fused k/q/v projection (3xTF32 wmma) ----------------
// block: 256 threads, 128 gathered rows x 128 cols
__global__ void __launch_bounds__(256, 2) proj_kqv_kernel(
    const float* __restrict__ h,
    const float* __restrict__ kw, const float* __restrict__ qw, const float* __restrict__ vw,
    float* __restrict__ ok, float* __restrict__ oq, float* __restrict__ ov)
{
    extern __shared__ float sm[];
    float* As = sm;
    float* Bs = sm + SM_AS;          // also C staging (64 rows)
    __shared__ int rows_s[128];

    int tid = threadIdx.x, wid = tid >> 5;
    int t = blockIdx.y;
    int base = g_off[t];
    int cnt = g_off[t+1] - base;
    int tb = blockIdx.x * 128;
    if (tb >= cnt) return;
    int mc = min(128, cnt - tb);

    if (tid < 128) rows_s[tid] = (tid < mc) ? g_bucket[base + tb + tid] : 0;
    __syncthreads();

    // stage gathered A rows (zeros beyond mc)
    #pragma unroll
    for (int i = 0; i < 16; i++){
        int idx = tid + i*256;           // 0..4095
        int m = idx >> 5, c4 = idx & 31;
        float4 v = make_float4(0.f,0.f,0.f,0.f);
        if (m < mc) v = *reinterpret_cast<const float4*>(h + (size_t)rows_s[m]*128 + c4*4);
        *reinterpret_cast<float4*>(As + m*AS_LD + c4*4) = v;
    }

    const float* Wsrc[3] = { kw + t*16384, qw + t*16384, vw + t*16384 };
    float* Cd[3] = { ok, oq, ov };
    int wrow0 = wid * 16;

    for (int w = 0; w < 3; w++){
        FragC cf[8];
        #pragma unroll
        for (int nt = 0; nt < 8; nt++) wmma::fill_fragment(cf[nt], 0.f);

        for (int ch = 0; ch < 2; ch++){
            __syncthreads();
            stage_B(Bs, Wsrc[w] + ch*64*128, tid);
            __syncthreads();
            mma_chunk(As, Bs, cf, wrow0, ch*64);
        }

        // two-phase writeback via Bs as C staging (64 rows each)
        float* Cdst = Cd[w];
        for (int ph = 0; ph < 2; ph++){
            __syncthreads();
            if ((wid >> 2) == ph){
                int lr0 = (wid & 3) * 16;
                #pragma unroll
                for (int nt = 0; nt < 8; nt++)
                    wmma::store_matrix_sync(Bs + lr0*BS_LD + nt*16, cf[nt], BS_LD, wmma::mem_row_major);
            }
            __syncthreads();
            #pragma unroll
            for (int i = 0; i < 8; i++){
                int idx = tid + i*256;       // 0..2047
                int m = idx >> 5, c4 = idx & 31;
                int gm = ph*64 + m;
                if (gm < mc){
                    float4 v = *reinterpret_cast<const float4*>(Bs + m*BS_LD + c4*4);
                    *reinterpret_cast<float4*>(Cdst + (size_t)rows_s[gm]*128 + c4*4) = v;
                }
            }
        }
        __syncthreads();
    }
}

// ---------------- K2: per-relation dense GEMM (3xTF32 wmma), direct gmem store ----------------
// grid: (NT, Rr, 2)  z=0: kA = k @ att[r], z=1: vM = v @ msg[r]
__global__ void __launch_bounds__(256, 2) relproj_kernel(
    const float* __restrict__ Xk, const float* __restrict__ Xv,
    const float* __restrict__ att, const float* __restrict__ msg,
    float* __restrict__ CkA, float* __restrict__ CvM)
{
    extern __shared__ float sm[];
    float* As = sm;
    float* Bs = sm + SM_AS;

    int tid = threadIdx.x, wid = tid >> 5;
    int tile = blockIdx.x, r = blockIdx.y, z = blockIdx.z;
    const float* X = z ? Xv : Xk;
    const float* W = (z ? msg : att) + (size_t)r*16384;
    float* C = (z ? CvM : CkA) + (size_t)r*NP*128;

    int row0 = tile * 128;
    // stage A rows (padded region of X is pre-zeroed)
    #pragma unroll
    for (int i = 0; i < 16; i++){
        int idx = tid + i*256;
        int m = idx >> 5, c4 = idx & 31;
        float4 v = *reinterpret_cast<const float4*>(X + (size_t)(row0 + m)*128 + c4*4);
        *reinterpret_cast<float4*>(As + m*AS_LD + c4*4) = v;
    }

    FragC cf[8];
    #pragma unroll
    for (int nt = 0; nt < 8; nt++) wmma::fill_fragment(cf[nt], 0.f);

    int wrow0 = wid * 16;
    for (int ch = 0; ch < 2; ch++){
        __syncthreads();
        stage_B(Bs, W + ch*64*128, tid);
        __syncthreads();
        mma_chunk(As, Bs, cf, wrow0, ch*64);
    }

    float* Crow = C + (size_t)(row0 + wrow0)*128;
    #pragma unroll
    for (int nt = 0; nt < 8; nt++)
        wmma::store_matrix_sync(Crow + nt*16, cf[nt], 128, wmma::mem_row_major);
}

// zero pad rows of k/v so relproj A staging reads defined data
__global__ void zeropad_kernel(float* __restrict__ k, float* __restrict__ v){
    int i = blockIdx.x * 256 + threadIdx.x;   // (NP-Nn)*128 = 6144
    if (i < (NP - Nn)*128){
        k[(size_t)Nn*128 + i] = 0.f;
        v[(size_t)Nn*128 + i] = 0.f;
    }
}

// ---------------- K3: per-edge score + segment max ----------------
__global__ void __launch_bounds__(256) score_kernel(
    const float* __restrict__ kA, const float* __restrict__ q,
    const int* __restrict__ src, const int* __restrict__ dst, const int* __restrict__ et,
    const float* __restrict__ pri, float* __restrict__ score, unsigned* __restrict__ segmax)
{
    int e = (blockIdx.x * blockDim.x + threadIdx.x) >> 5;
    if (e >= Ee) return;
    int lane = threadIdx.x & 31;
    int s = src[e], d = dst[e], r = et[e];
    const float4* ka = reinterpret_cast<const float4*>(kA + ((size_t)r*NP + s)*128);
    const float4* qq = reinterpret_cast<const float4*>(q + (size_t)d*128);
    float4 x = ka[lane], y = qq[lane];
    float acc = x.x*y.x + x.y*y.y + x.z*y.z + x.w*y.w;
    #pragma unroll
    for (int o = 16; o; o >>= 1) acc += __shfl_xor_sync(0xffffffffu, acc, o);
    if (lane == 0){
        float sc = acc * pri[r] * 0.08838834764831845f;  // 1/sqrt(128)
        score[e] = sc;
        atomicMax(&segmax[d*Rr + r], ford(sc));
    }
}

// ---------------- K4: exp + denom ----------------
__global__ void __launch_bounds__(256) exp_kernel(
    const float* __restrict__ score, const int* __restrict__ dst, const int* __restrict__ et,
    const unsigned* __restrict__ segmax, float* __restrict__ denom, float* __restrict__ ex)
{
    int e = blockIdx.x * 256 + threadIdx.x;
    if (e >= Ee) return;
    int seg = dst[e]*Rr + et[e];
    float m = ordf(segmax[seg]);
    float v = expf(score[e] - m);
    ex[e] = v;
    atomicAdd(&denom[seg], v);
}

// ---------------- K5: weighted aggregation (vector red) ----------------
__global__ void __launch_bounds__(256) agg_kernel(
    const float* __restrict__ vM, const float* __restrict__ ex, const float* __restrict__ denom,
    const int* __restrict__ src, const int* __restrict__ dst, const int* __restrict__ et,
    float* __restrict__ agg)
{
    int e = (blockIdx.x * blockDim.x + threadIdx.x) >> 5;
    if (e >= Ee) return;
    int lane = threadIdx.x & 31;
    int s = src[e], d = dst[e], r = et[e];
    float alpha = ex[e] / denom[d*Rr + r];
    const float4* vm = reinterpret_cast<const float4*>(vM + ((size_t)r*NP + s)*128);
    float4 v = vm[lane];
    float* out = agg + (size_t)d*128 + lane*4;
    asm volatile("red.global.add.v4.f32 [%0], {%1, %2, %3, %4};"
                 :: "l"(out), "f"(alpha*v.x), "f"(alpha*v.y), "f"(alpha*v.z), "f"(alpha*v.w)
                 : "memory");
}

// ---------------- K6: per-type output transform with sigmoid(skip) gate ----------------
__global__ void __launch_bounds__(256, 2) out_kernel(
    const float* __restrict__ agg, const float* __restrict__ aw,
    const float* __restrict__ skip, float* __restrict__ out)
{
    extern __shared__ float sm[];
    float* As = sm;
    float* Bs = sm + SM_AS;
    __shared__ int rows_s[128];

    int tid = threadIdx.x, wid = tid >> 5;
    int t = blockIdx.y;
    int base = g_off[t];
    int cnt = g_off[t+1] - base;
    int tb = blockIdx.x * 128;
    if (tb >= cnt) return;
    int mc = min(128, cnt - tb);

    if (tid < 128) rows_s[tid] = (tid < mc) ? g_bucket[base + tb + tid] : 0;
    __syncthreads();

    #pragma unroll
    for (int i = 0; i < 16; i++){
        int idx = tid + i*256;
        int m = idx >> 5, c4 = idx & 31;
        float4 v = make_float4(0.f,0.f,0.f,0.f);
        if (m < mc) v = *reinterpret_cast<const float4*>(agg + (size_t)rows_s[m]*128 + c4*4);
        *reinterpret_cast<float4*>(As + m*AS_LD + c4*4) = v;
    }

    FragC cf[8];
    #pragma unroll
    for (int nt = 0; nt < 8; nt++) wmma::fill_fragment(cf[nt], 0.f);

    int wrow0 = wid * 16;
    const float* W = aw + (size_t)t*16384;
    for (int ch = 0; ch < 2; ch++){
        __syncthreads();
        stage_B(Bs, W + ch*64*128, tid);
        __syncthreads();
        mma_chunk(As, Bs, cf, wrow0, ch*64);
    }

    float gate = 1.f / (1.f + expf(-skip[t]));
    for (int ph = 0; ph < 2; ph++){
        __syncthreads();
        if ((wid >> 2) == ph){
            int lr0 = (wid & 3) * 16;
            #pragma unroll
            for (int nt = 0; nt < 8; nt++)
                wmma::store_matrix_sync(Bs + lr0*BS_LD + nt*16, cf[nt], BS_LD, wmma::mem_row_major);
        }
        __syncthreads();
        #pragma unroll
        for (int i = 0; i < 8; i++){
            int idx = tid + i*256;
            int m = idx >> 5, c4 = idx & 31;
            int gm = ph*64 + m;
            if (gm < mc){
                float4 v = *reinterpret_cast<const float4*>(Bs + m*BS_LD + c4*4);
                v.x *= gate; v.y *= gate; v.z *= gate; v.w *= gate;
                *reinterpret_cast<float4*>(out + (size_t)rows_s[gm]*128 + c4*4) = v;
            }
        }
    }
}

// ---------------- launch ----------------
extern "C" void kernel_launch(void* const* d_in, const int* in_sizes, int n_in,
                              void* d_out, int out_size)
{
    const float* h     = (const float*)d_in[0];
    const int*   adj   = (const int*)d_in[1];
    const int*   etype = (const int*)d_in[2];
    const int*   ntype = (const int*)d_in[3];
    const float* kw    = (const float*)d_in[6];
    const float* qw    = (const float*)d_in[7];
    const float* vw    = (const float*)d_in[8];
    const float* aw    = (const float*)d_in[9];
    const float* pri   = (const float*)d_in[10];
    const float* att   = (const float*)d_in[11];
    const float* msg   = (const float*)d_in[12];
    const float* skip  = (const float*)d_in[13];
    const int* src = adj;
    const int* dst = adj + Ee;
    float* out = (float*)d_out;

    cudaFuncSetAttribute(proj_kqv_kernel, cudaFuncAttributeMaxDynamicSharedMemorySize, GEMM_SMEM);
    cudaFuncSetAttribute(relproj_kernel,  cudaFuncAttributeMaxDynamicSharedMemorySize, GEMM_SMEM);
    cudaFuncSetAttribute(out_kernel,      cudaFuncAttributeMaxDynamicSharedMemorySize, GEMM_SMEM);

    void *pk, *pq, *pv, *pkA, *pvM, *pscore, *pex, *psegmax, *pdenom, *pagg;
    cudaGetSymbolAddress(&pk, g_k);
    cudaGetSymbolAddress(&pq, g_q);
    cudaGetSymbolAddress(&pv, g_v);
    cudaGetSymbolAddress(&pkA, g_kA);
    cudaGetSymbolAddress(&pvM, g_vM);
    cudaGetSymbolAddress(&pscore, g_score);
    cudaGetSymbolAddress(&pex, g_ex);
    cudaGetSymbolAddress(&psegmax, g_segmax);
    cudaGetSymbolAddress(&pdenom, g_denom);
    cudaGetSymbolAddress(&pagg, g_agg);

    // init + bucketing
    init_kernel<<<(Nn*128 + 255)/256, 256>>>();
    hist_kernel<<<(Nn + 255)/256, 256>>>(ntype);
    prefix_kernel<<<1, 32>>>();
    scatter_kernel<<<(Nn + 255)/256, 256>>>(ntype);
    zeropad_kernel<<<((NP - Nn)*128 + 255)/256, 256>>>((float*)pk, (float*)pv);

    // k/q/v projections (3xTF32 tensor-core)
    dim3 gT((Nn + 127)/128, Tt);
    proj_kqv_kernel<<<gT, 256, GEMM_SMEM>>>(h, kw, qw, vw,
                                            (float*)pk, (float*)pq, (float*)pv);

    // per-relation GEMMs (3xTF32 tensor-core), k->kA and v->vM fused in one grid
    dim3 gR(NT, Rr, 2);
    relproj_kernel<<<gR, 256, GEMM_SMEM>>>((const float*)pk, (const float*)pv,
                                           att, msg, (float*)pkA, (float*)pvM);

    int score_blocks = (Ee + 7) / 8;
    score_kernel<<<score_blocks, 256>>>((const float*)pkA, (const float*)pq,
                                        src, dst, etype, pri,
                                        (float*)pscore, (unsigned*)psegmax);

    exp_kernel<<<(Ee + 255)/256, 256>>>((const float*)pscore, dst, etype,
                                        (const unsigned*)psegmax,
                                        (float*)pdenom, (float*)pex);

    agg_kernel<<<score_blocks, 256>>>((const float*)pvM, (const float*)pex,
                                      (const float*)pdenom, src, dst, etype,
                                      (float*)pagg);

    out_kernel<<<gT, 256, GEMM_SMEM>>>((const float*)pagg, aw, skip, out);
}